// round 16
// baseline (speedup 1.0000x reference)
#include <cuda_runtime.h>
#include <cuda_bf16.h>
#include <cuda_fp16.h>
#include <cstdint>
#include <math.h>

#define BB 4
#define TT 2048
#define CC 1024
#define HH 16
#define HD 64
#define MM (BB*TT)
#define QS 72   // attn smem row stride in bf16 (144B): LDSM-conflict-free

// ---------------- scratch (static device arrays; no cudaMalloc) -------------
__device__ __nv_bfloat16 g_Qh[BB*HH*TT*HD], g_Ql[BB*HH*TT*HD];
__device__ __nv_bfloat16 g_Kh[BB*HH*TT*HD], g_Kl[BB*HH*TT*HD];
__device__ __nv_bfloat16 g_Vh[BB*HH*TT*HD], g_Vl[BB*HH*TT*HD];

__device__ __half        g_xh[MM*CC],     g_xl[MM*CC];     // x: fp16 hi/lo
__device__ __half        g_wqh[3*CC*CC];                   // qkv_w: fp16 (single)
__device__ __nv_bfloat16 g_woh[CC*CC],    g_wol[CC*CC];    // out_w: bf16 hi/lo
__device__ __nv_bfloat16 g_ah[MM*CC],     g_al[MM*CC];     // attn out: bf16 hi/lo

// D(f32) += A * B
#define MMA_BF16(acc, a, b) \
    asm("mma.sync.aligned.m16n8k16.row.col.f32.bf16.bf16.f32 " \
        "{%0,%1,%2,%3}, {%4,%5,%6,%7}, {%8,%9}, {%0,%1,%2,%3};" \
        : "+f"((acc)[0]), "+f"((acc)[1]), "+f"((acc)[2]), "+f"((acc)[3]) \
        : "r"((a)[0]), "r"((a)[1]), "r"((a)[2]), "r"((a)[3]), "r"((b)[0]), "r"((b)[1]))
#define MMA_F16(acc, a, b) \
    asm("mma.sync.aligned.m16n8k16.row.col.f32.f16.f16.f32 " \
        "{%0,%1,%2,%3}, {%4,%5,%6,%7}, {%8,%9}, {%0,%1,%2,%3};" \
        : "+f"((acc)[0]), "+f"((acc)[1]), "+f"((acc)[2]), "+f"((acc)[3]) \
        : "r"((a)[0]), "r"((a)[1]), "r"((a)[2]), "r"((a)[3]), "r"((b)[0]), "r"((b)[1]))

#define LDSM_X4(r, addr) \
    asm volatile("ldmatrix.sync.aligned.m8n8.x4.shared.b16 {%0,%1,%2,%3}, [%4];" \
        : "=r"((r)[0]), "=r"((r)[1]), "=r"((r)[2]), "=r"((r)[3]) : "r"(addr))
#define LDSM_X4_T(r, addr) \
    asm volatile("ldmatrix.sync.aligned.m8n8.x4.trans.shared.b16 {%0,%1,%2,%3}, [%4];" \
        : "=r"((r)[0]), "=r"((r)[1]), "=r"((r)[2]), "=r"((r)[3]) : "r"(addr))

__device__ __forceinline__ unsigned smem_u32(const void* p) {
    return (unsigned)__cvta_generic_to_shared(p);
}
__device__ __forceinline__ unsigned pack_bf(__nv_bfloat16 lo, __nv_bfloat16 hi) {
    return ((unsigned)__bfloat16_as_ushort(hi) << 16) | __bfloat16_as_ushort(lo);
}

// ---------------------------------------------------------------------------
// splits (destinations bound in device code)
// ---------------------------------------------------------------------------
template<int DST>
__global__ __launch_bounds__(256)
void split_kernel(const float4* __restrict__ src, int n4)
{
    int i = blockIdx.x * blockDim.x + threadIdx.x;
    if (i >= n4) return;
    float4 v = src[i];
    if (DST == 0) {
        ushort4 h, l;
#define SPLH(c, hc, lc) { \
        __half hb = __float2half_rn(v.c); \
        __half lb = __float2half_rn(v.c - __half2float(hb)); \
        hc = __half_as_ushort(hb); lc = __half_as_ushort(lb); }
        SPLH(x, h.x, l.x) SPLH(y, h.y, l.y) SPLH(z, h.z, l.z) SPLH(w, h.w, l.w)
        ((ushort4*)g_xh)[i] = h; ((ushort4*)g_xl)[i] = l;
    } else if (DST == 1) {
        ushort4 h;
        h.x = __half_as_ushort(__float2half_rn(v.x));
        h.y = __half_as_ushort(__float2half_rn(v.y));
        h.z = __half_as_ushort(__float2half_rn(v.z));
        h.w = __half_as_ushort(__float2half_rn(v.w));
        ((ushort4*)g_wqh)[i] = h;
    } else {
        ushort4 h, l;
#define SPLB(c, hc, lc) { \
        __nv_bfloat16 hb = __float2bfloat16_rn(v.c); \
        __nv_bfloat16 lb = __float2bfloat16_rn(v.c - __bfloat162float(hb)); \
        hc = __bfloat16_as_ushort(hb); lc = __bfloat16_as_ushort(lb); }
        SPLB(x, h.x, l.x) SPLB(y, h.y, l.y) SPLB(z, h.z, l.z) SPLB(w, h.w, l.w)
        ((ushort4*)g_woh)[i] = h; ((ushort4*)g_wol)[i] = l;
    }
}

// ---------------------------------------------------------------------------
// QKV GEMM (fp16x2): CTA 128x256, 8 warps (2x4), warp tile 64x64.
// Per k16 step: 8 A-LDSM + 4 B-LDSM for 64 MMAs (ratio 0.19 vs 0.31 before).
// smem 40KB static: Ah/Al 128x20w each, B 256x20w.
// ---------------------------------------------------------------------------
__global__ __launch_bounds__(256)
void gemm_qkv(const float* __restrict__ bias)
{
    __shared__ unsigned sAh[128][20], sAl[128][20], sB[256][20];

    const int tid  = threadIdx.x;
    const int warp = tid >> 5;
    const int lane = tid & 31;
    const int g = lane >> 2;
    const int t = lane & 3;
    const int wm = (warp & 1) * 64;
    const int wn = (warp >> 1) * 64;
    const int m0 = blockIdx.y * 128;
    const int n0 = blockIdx.x * 256;

    const int lrow = tid >> 1;
    const int loff = (tid & 1) * 8;   // word offset within 16-word payload

    const __nv_bfloat16* Ap  = (const __nv_bfloat16*)g_xh  + (size_t)(m0 + lrow) * CC + loff * 2;
    const __nv_bfloat16* Alp = (const __nv_bfloat16*)g_xl  + (size_t)(m0 + lrow) * CC + loff * 2;
    const __nv_bfloat16* Bp0 = (const __nv_bfloat16*)g_wqh + (size_t)(n0 + lrow) * CC + loff * 2;
    const __nv_bfloat16* Bp1 = (const __nv_bfloat16*)g_wqh + (size_t)(n0 + 128 + lrow) * CC + loff * 2;

    const unsigned aOff = (unsigned)(wm + (lane & 15)) * 80u + (unsigned)(lane >> 4) * 16u;
    const unsigned bOff = (unsigned)(wn + (lane & 15)) * 80u + (unsigned)(lane >> 4) * 16u;
    const unsigned baseAh = smem_u32(sAh) + aOff;
    const unsigned baseAl = smem_u32(sAl) + aOff;
    const unsigned baseB  = smem_u32(sB)  + bOff;

    float acc[4][8][4];
    #pragma unroll
    for (int i = 0; i < 4; ++i)
        #pragma unroll
        for (int j = 0; j < 8; ++j)
            #pragma unroll
            for (int e = 0; e < 4; ++e) acc[i][j][e] = 0.f;

    uint4 rah0, rah1, ral0, ral1, rb00, rb01, rb10, rb11;
#define LOAD_STAGE(kt) { \
        const int eo = (kt) * 32; \
        rah0 = *(const uint4*)(Ap  + eo); rah1 = *(const uint4*)(Ap  + eo + 8); \
        ral0 = *(const uint4*)(Alp + eo); ral1 = *(const uint4*)(Alp + eo + 8); \
        rb00 = *(const uint4*)(Bp0 + eo); rb01 = *(const uint4*)(Bp0 + eo + 8); \
        rb10 = *(const uint4*)(Bp1 + eo); rb11 = *(const uint4*)(Bp1 + eo + 8); }

    LOAD_STAGE(0);

    #pragma unroll 1
    for (int kt = 0; kt < 32; ++kt) {
        *(uint4*)&sAh[lrow][loff]       = rah0; *(uint4*)&sAh[lrow][loff + 4]       = rah1;
        *(uint4*)&sAl[lrow][loff]       = ral0; *(uint4*)&sAl[lrow][loff + 4]       = ral1;
        *(uint4*)&sB[lrow][loff]        = rb00; *(uint4*)&sB[lrow][loff + 4]        = rb01;
        *(uint4*)&sB[128 + lrow][loff]  = rb10; *(uint4*)&sB[128 + lrow][loff + 4]  = rb11;
        __syncthreads();

        if (kt + 1 < 32) LOAD_STAGE(kt + 1);

        #pragma unroll
        for (int ks = 0; ks < 2; ++ks) {
            const unsigned ko = (unsigned)ks * 32u;

            unsigned ah[4][4], al[4][4], b4[4][4];
            #pragma unroll
            for (int mt = 0; mt < 4; ++mt) {
                LDSM_X4(ah[mt], baseAh + (unsigned)mt * 1280u + ko);
                LDSM_X4(al[mt], baseAl + (unsigned)mt * 1280u + ko);
            }
            #pragma unroll
            for (int p = 0; p < 4; ++p)
                LDSM_X4(b4[p], baseB + (unsigned)p * 1280u + ko);

            #pragma unroll
            for (int mt = 0; mt < 4; ++mt)
                #pragma unroll
                for (int nt = 0; nt < 8; ++nt) {
                    const int p = nt >> 1, q = nt & 1;
                    unsigned bb[2] = { b4[p][q], b4[p][q + 2] };
                    MMA_F16(acc[mt][nt], ah[mt], bb);
                    MMA_F16(acc[mt][nt], al[mt], bb);
                }
        }
        __syncthreads();
    }

    #pragma unroll
    for (int mt = 0; mt < 4; ++mt)
        #pragma unroll
        for (int nt = 0; nt < 8; ++nt)
            #pragma unroll
            for (int i = 0; i < 4; ++i) {
                const int m = m0 + wm + mt * 16 + g + (i >> 1) * 8;
                const int n = n0 + wn + nt * 8 + t * 2 + (i & 1);
                float v = acc[mt][nt][i] + bias[n];
                const int which = n >> 10;          // 0=q 1=k 2=v
                const int hc = n & 1023;
                const int h  = hc >> 6;
                const int d  = hc & 63;
                const int b  = m >> 11;
                const int tt = m & (TT - 1);
                __nv_bfloat16* dh = (which == 0) ? g_Qh : (which == 1) ? g_Kh : g_Vh;
                __nv_bfloat16* dl = (which == 0) ? g_Ql : (which == 1) ? g_Kl : g_Vl;
                if (which == 0) v *= 0.125f;        // 1/sqrt(64)
                __nv_bfloat16 hb = __float2bfloat16_rn(v);
                __nv_bfloat16 lb = __float2bfloat16_rn(v - __bfloat162float(hb));
                const size_t off = (size_t)((b*HH + h)*TT + tt) * HD + d;
                dh[off] = hb; dl[off] = lb;
            }
}

// ---------------------------------------------------------------------------
// Out-projection GEMM (bf16x3, mma.sync) — unchanged from R14 (passing).
// ---------------------------------------------------------------------------
__global__ __launch_bounds__(256)
void gemm_out(const float* __restrict__ bias, float* __restrict__ out)
{
    __shared__ unsigned sAh[128][20], sAl[128][20], sBh[128][20], sBl[128][20];

    const int tid  = threadIdx.x;
    const int warp = tid >> 5;
    const int lane = tid & 31;
    const int g = lane >> 2;
    const int t = lane & 3;
    const int wm = (warp & 1) * 64;
    const int wn = (warp >> 1) * 32;
    const int m0 = blockIdx.y * 128;
    const int n0 = blockIdx.x * 128;

    const int lrow = tid >> 1;
    const int loff = (tid & 1) * 8;

    const __nv_bfloat16* Ap  = g_ah  + (size_t)(m0 + lrow) * CC + loff * 2;
    const __nv_bfloat16* Alp = g_al  + (size_t)(m0 + lrow) * CC + loff * 2;
    const __nv_bfloat16* Bp  = g_woh + (size_t)(n0 + lrow) * CC + loff * 2;
    const __nv_bfloat16* Blp = g_wol + (size_t)(n0 + lrow) * CC + loff * 2;

    const unsigned aOff = (unsigned)(wm + (lane & 15)) * 80u + (unsigned)(lane >> 4) * 16u;
    const unsigned bOff = (unsigned)(wn + (lane & 15)) * 80u + (unsigned)(lane >> 4) * 16u;
    const unsigned baseAh = smem_u32(sAh) + aOff;
    const unsigned baseAl = smem_u32(sAl) + aOff;
    const unsigned baseBh = smem_u32(sBh) + bOff;
    const unsigned baseBl = smem_u32(sBl) + bOff;

    float acc[4][4][4];
    #pragma unroll
    for (int i = 0; i < 4; ++i)
        #pragma unroll
        for (int j = 0; j < 4; ++j)
            #pragma unroll
            for (int e = 0; e < 4; ++e) acc[i][j][e] = 0.f;

    uint4 rah0, rah1, ral0, ral1, rbh0, rbh1, rbl0, rbl1;
#define LOAD_STAGE_O(kt) { \
        const int eo = (kt) * 32; \
        rah0 = *(const uint4*)(Ap  + eo); rah1 = *(const uint4*)(Ap  + eo + 8); \
        ral0 = *(const uint4*)(Alp + eo); ral1 = *(const uint4*)(Alp + eo + 8); \
        rbh0 = *(const uint4*)(Bp  + eo); rbh1 = *(const uint4*)(Bp  + eo + 8); \
        rbl0 = *(const uint4*)(Blp + eo); rbl1 = *(const uint4*)(Blp + eo + 8); }

    LOAD_STAGE_O(0);

    #pragma unroll 1
    for (int kt = 0; kt < 32; ++kt) {
        *(uint4*)&sAh[lrow][loff]     = rah0; *(uint4*)&sAh[lrow][loff + 4] = rah1;
        *(uint4*)&sAl[lrow][loff]     = ral0; *(uint4*)&sAl[lrow][loff + 4] = ral1;
        *(uint4*)&sBh[lrow][loff]     = rbh0; *(uint4*)&sBh[lrow][loff + 4] = rbh1;
        *(uint4*)&sBl[lrow][loff]     = rbl0; *(uint4*)&sBl[lrow][loff + 4] = rbl1;
        __syncthreads();

        if (kt + 1 < 32) LOAD_STAGE_O(kt + 1);

        #pragma unroll
        for (int ks = 0; ks < 2; ++ks) {
            const unsigned ko = (unsigned)ks * 32u;

            unsigned ah[4][4], al[4][4], bh4[2][4], bl4[2][4];
            #pragma unroll
            for (int mt = 0; mt < 4; ++mt) {
                LDSM_X4(ah[mt], baseAh + (unsigned)mt * 1280u + ko);
                LDSM_X4(al[mt], baseAl + (unsigned)mt * 1280u + ko);
            }
            #pragma unroll
            for (int p = 0; p < 2; ++p) {
                LDSM_X4(bh4[p], baseBh + (unsigned)p * 1280u + ko);
                LDSM_X4(bl4[p], baseBl + (unsigned)p * 1280u + ko);
            }
            #pragma unroll
            for (int mt = 0; mt < 4; ++mt)
                #pragma unroll
                for (int nt = 0; nt < 4; ++nt) {
                    const int p = nt >> 1, q = nt & 1;
                    unsigned bh[2] = { bh4[p][q], bh4[p][q + 2] };
                    unsigned bl[2] = { bl4[p][q], bl4[p][q + 2] };
                    MMA_BF16(acc[mt][nt], ah[mt], bh);
                    MMA_BF16(acc[mt][nt], ah[mt], bl);
                    MMA_BF16(acc[mt][nt], al[mt], bh);
                }
        }
        __syncthreads();
    }

    #pragma unroll
    for (int mt = 0; mt < 4; ++mt)
        #pragma unroll
        for (int nt = 0; nt < 4; ++nt)
            #pragma unroll
            for (int i = 0; i < 4; ++i) {
                const int m = m0 + wm + mt * 16 + g + (i >> 1) * 8;
                const int n = n0 + wn + nt * 8 + t * 2 + (i & 1);
                out[(size_t)m * CC + n] = acc[mt][nt][i] + bias[n];
            }
}

// ---------------------------------------------------------------------------
// Tensor-core causal flash attention (bf16x3) — unchanged from R14 (passing).
// ---------------------------------------------------------------------------
__global__ __launch_bounds__(128)
void attn_mma()
{
    __shared__ __align__(16) __nv_bfloat16 sQh[64*QS], sQl[64*QS];
    __shared__ __align__(16) __nv_bfloat16 sKVh[64*QS], sKVl[64*QS];

    const int tid  = threadIdx.x;
    const int warp = tid >> 5;
    const int lane = tid & 31;
    const int g = lane >> 2;
    const int t = lane & 3;
    const int q0 = blockIdx.x * 64;
    const int bh = blockIdx.y;
    const size_t gbase = (size_t)bh * TT * HD;

    #pragma unroll
    for (int idx = tid; idx < 512; idx += 128) {
        const int r = idx >> 3, c = idx & 7;
        const size_t go = gbase + (size_t)(q0 + r) * HD + c * 8;
        *(uint4*)&sQh[r*QS + c*8] = *(const uint4*)&g_Qh[go];
        *(uint4*)&sQl[r*QS + c*8] = *(const uint4*)&g_Ql[go];
    }

    const unsigned qOff = (unsigned)(warp*16 + (lane & 15)) * 144u + (unsigned)(lane >> 4) * 16u;
    const unsigned kOff = (unsigned)(((lane >> 4) & 1) * 8 + (lane & 7)) * 144u
                        + (unsigned)((lane >> 3) & 1) * 16u;
    const unsigned vOff = (unsigned)(((lane >> 3) & 1) * 8 + (lane & 7)) * 144u
                        + (unsigned)((lane >> 4) & 1) * 16u;
    const unsigned qbh = smem_u32(sQh)  + qOff, qbl = smem_u32(sQl)  + qOff;
    const unsigned kbh = smem_u32(sKVh) + kOff, kbl = smem_u32(sKVl) + kOff;
    const unsigned vbh = smem_u32(sKVh) + vOff, vbl = smem_u32(sKVl) + vOff;

    float m_i[2] = {-1e30f, -1e30f}, l_i[2] = {0.f, 0.f};
    float oacc[8][4];
    #pragma unroll
    for (int i = 0; i < 8; ++i)
        #pragma unroll
        for (int e = 0; e < 4; ++e) oacc[i][e] = 0.f;

    #pragma unroll 1
    for (int j0 = 0; j0 <= q0; j0 += 64) {
        __syncthreads();
        #pragma unroll
        for (int idx = tid; idx < 512; idx += 128) {
            const int r = idx >> 3, c = idx & 7;
            const size_t go = gbase + (size_t)(j0 + r) * HD + c * 8;
            *(uint4*)&sKVh[r*QS + c*8] = *(const uint4*)&g_Kh[go];
            *(uint4*)&sKVl[r*QS + c*8] = *(const uint4*)&g_Kl[go];
        }
        __syncthreads();

        float sacc[8][4];
        #pragma unroll
        for (int i = 0; i < 8; ++i)
            #pragma unroll
            for (int e = 0; e < 4; ++e) sacc[i][e] = 0.f;

        #pragma unroll
        for (int kc = 0; kc < 4; ++kc) {
            unsigned qh[4], ql[4];
            LDSM_X4(qh, qbh + kc*32u);
            LDSM_X4(ql, qbl + kc*32u);
            #pragma unroll
            for (int ntp = 0; ntp < 4; ++ntp) {
                unsigned kh[4], kl[4];
                LDSM_X4(kh, kbh + (unsigned)ntp*2304u + kc*32u);
                LDSM_X4(kl, kbl + (unsigned)ntp*2304u + kc*32u);
                MMA_BF16(sacc[2*ntp],   qh, kh);
                MMA_BF16(sacc[2*ntp],   qh, kl);
                MMA_BF16(sacc[2*ntp],   ql, kh);
                MMA_BF16(sacc[2*ntp+1], qh, kh + 2);
                MMA_BF16(sacc[2*ntp+1], qh, kl + 2);
                MMA_BF16(sacc[2*ntp+1], ql, kh + 2);
            }
        }

        if (j0 == q0) {
            const int rbase = q0 + warp*16;
            #pragma unroll
            for (int nt = 0; nt < 8; ++nt)
                #pragma unroll
                for (int e = 0; e < 4; ++e) {
                    const int col = j0 + nt*8 + t*2 + (e & 1);
                    const int row = rbase + g + (e >> 1)*8;
                    if (col > row) sacc[nt][e] = -1e30f;
                }
        }

        #pragma unroll
        for (int h2 = 0; h2 < 2; ++h2) {
            float mloc = -1e30f;
            #pragma unroll
            for (int nt = 0; nt < 8; ++nt)
                mloc = fmaxf(mloc, fmaxf(sacc[nt][2*h2], sacc[nt][2*h2+1]));
            mloc = fmaxf(mloc, __shfl_xor_sync(0xffffffffu, mloc, 1));
            mloc = fmaxf(mloc, __shfl_xor_sync(0xffffffffu, mloc, 2));
            const float mnew = fmaxf(m_i[h2], mloc);
            const float corr = __expf(m_i[h2] - mnew);
            float sum = 0.f;
            #pragma unroll
            for (int nt = 0; nt < 8; ++nt) {
                const float p0 = __expf(sacc[nt][2*h2]   - mnew);
                const float p1 = __expf(sacc[nt][2*h2+1] - mnew);
                sacc[nt][2*h2] = p0; sacc[nt][2*h2+1] = p1;
                sum += p0 + p1;
            }
            sum += __shfl_xor_sync(0xffffffffu, sum, 1);
            sum += __shfl_xor_sync(0xffffffffu, sum, 2);
            l_i[h2] = l_i[h2] * corr + sum;
            m_i[h2] = mnew;
            #pragma unroll
            for (int dt = 0; dt < 8; ++dt) {
                oacc[dt][2*h2] *= corr; oacc[dt][2*h2+1] *= corr;
            }
        }

        __syncthreads();
        #pragma unroll
        for (int idx = tid; idx < 512; idx += 128) {
            const int r = idx >> 3, c = idx & 7;
            const size_t go = gbase + (size_t)(j0 + r) * HD + c * 8;
            *(uint4*)&sKVh[r*QS + c*8] = *(const uint4*)&g_Vh[go];
            *(uint4*)&sKVl[r*QS + c*8] = *(const uint4*)&g_Vl[go];
        }
        __syncthreads();

        #pragma unroll
        for (int kc = 0; kc < 4; ++kc) {
            unsigned ph[4], pl[4];
            #pragma unroll
            for (int u = 0; u < 4; ++u) {
                const int nt = 2*kc + (u >> 1);
                const float a0 = sacc[nt][(u & 1)*2], a1 = sacc[nt][(u & 1)*2 + 1];
                const __nv_bfloat16 h0 = __float2bfloat16_rn(a0);
                const __nv_bfloat16 h1 = __float2bfloat16_rn(a1);
                ph[u] = pack_bf(h0, h1);
                pl[u] = pack_bf(__float2bfloat16_rn(a0 - __bfloat162float(h0)),
                                __float2bfloat16_rn(a1 - __bfloat162float(h1)));
            }
            #pragma unroll
            for (int dtp = 0; dtp < 4; ++dtp) {
                unsigned vh[4], vl[4];
                LDSM_X4_T(vh, vbh + (unsigned)kc*2304u + dtp*32u);
                LDSM_X4_T(vl, vbl + (unsigned)kc*2304u + dtp*32u);
                MMA_BF16(oacc[2*dtp],   ph, vh);
                MMA_BF16(oacc[2*dtp],   ph, vl);
                MMA_BF16(oacc[2*dtp],   pl, vh);
                MMA_BF16(oacc[2*dtp+1], ph, vh + 2);
                MMA_BF16(oacc[2*dtp+1], ph, vl + 2);
                MMA_BF16(oacc[2*dtp+1], pl, vh + 2);
            }
        }
    }

    const int b  = bh >> 4;
    const int hh = bh & 15;
    #pragma unroll
    for (int h2 = 0; h2 < 2; ++h2) {
        const float inv = 1.f / l_i[h2];
        const int r = q0 + warp*16 + g + h2*8;
        const size_t rowoff = (size_t)(b*TT + r) * CC + hh*HD;
        #pragma unroll
        for (int dt = 0; dt < 8; ++dt) {
            const float o0 = oacc[dt][2*h2] * inv;
            const float o1 = oacc[dt][2*h2+1] * inv;
            const __nv_bfloat16 h0 = __float2bfloat16_rn(o0);
            const __nv_bfloat16 h1 = __float2bfloat16_rn(o1);
            const unsigned wh = pack_bf(h0, h1);
            const unsigned wl = pack_bf(__float2bfloat16_rn(o0 - __bfloat162float(h0)),
                                        __float2bfloat16_rn(o1 - __bfloat162float(h1)));
            *(unsigned*)&g_ah[rowoff + dt*8 + t*2] = wh;
            *(unsigned*)&g_al[rowoff + dt*8 + t*2] = wl;
        }
    }
}

// ---------------------------------------------------------------------------
extern "C" void kernel_launch(void* const* d_in, const int* in_sizes, int n_in,
                              void* d_out, int out_size)
{
    const float* x     = (const float*)d_in[0];
    const float* qkv_b = (const float*)d_in[2];
    const float* out_b = (const float*)d_in[4];
    float* y = (float*)d_out;

    {
        int n4 = MM*CC/4;
        split_kernel<0><<<(n4+255)/256, 256>>>((const float4*)x, n4);
    }
    {
        int n4 = 3*CC*CC/4;
        split_kernel<1><<<(n4+255)/256, 256>>>((const float4*)d_in[1], n4);
    }
    {
        int n4 = CC*CC/4;
        split_kernel<2><<<(n4+255)/256, 256>>>((const float4*)d_in[3], n4);
    }

    // 1) QKV projection (fp16x2, wide warp tile) -> Q/K/V bf16 hi/lo
    gemm_qkv<<<dim3(3*CC/256, MM/128), 256>>>(qkv_b);
    // 2) causal attention (bf16x3) -> g_ah/g_al
    attn_mma<<<dim3(TT/64, BB*HH), 128>>>();
    // 3) output projection (bf16x3)
    gemm_out<<<dim3(CC/128, MM/128), 256>>>(out_b, y);
}

// round 17
// speedup vs baseline: 1.1821x; 1.1821x over previous
#include <cuda_runtime.h>
#include <cuda_bf16.h>
#include <cuda_fp16.h>
#include <cstdint>
#include <math.h>

#define BB 4
#define TT 2048
#define CC 1024
#define HH 16
#define HD 64
#define MM (BB*TT)
#define QS 72   // attn smem row stride in bf16 (144B): LDSM-conflict-free

// ---------------- scratch (static device arrays; no cudaMalloc) -------------
__device__ __nv_bfloat16 g_Qh[BB*HH*TT*HD], g_Ql[BB*HH*TT*HD];
__device__ __nv_bfloat16 g_Kh[BB*HH*TT*HD], g_Kl[BB*HH*TT*HD];
__device__ __nv_bfloat16 g_Vh[BB*HH*TT*HD], g_Vl[BB*HH*TT*HD];

__device__ __half        g_xh[MM*CC];                      // x: fp16 (single)
__device__ __half        g_wqh[3*CC*CC];                   // qkv_w: fp16 (single)
__device__ __nv_bfloat16 g_woh[CC*CC],    g_wol[CC*CC];    // out_w: bf16 hi/lo
__device__ __nv_bfloat16 g_ah[MM*CC],     g_al[MM*CC];     // attn out: bf16 hi/lo

// D(f32) += A * B
#define MMA_BF16(acc, a, b) \
    asm("mma.sync.aligned.m16n8k16.row.col.f32.bf16.bf16.f32 " \
        "{%0,%1,%2,%3}, {%4,%5,%6,%7}, {%8,%9}, {%0,%1,%2,%3};" \
        : "+f"((acc)[0]), "+f"((acc)[1]), "+f"((acc)[2]), "+f"((acc)[3]) \
        : "r"((a)[0]), "r"((a)[1]), "r"((a)[2]), "r"((a)[3]), "r"((b)[0]), "r"((b)[1]))
#define MMA_F16(acc, a, b) \
    asm("mma.sync.aligned.m16n8k16.row.col.f32.f16.f16.f32 " \
        "{%0,%1,%2,%3}, {%4,%5,%6,%7}, {%8,%9}, {%0,%1,%2,%3};" \
        : "+f"((acc)[0]), "+f"((acc)[1]), "+f"((acc)[2]), "+f"((acc)[3]) \
        : "r"((a)[0]), "r"((a)[1]), "r"((a)[2]), "r"((a)[3]), "r"((b)[0]), "r"((b)[1]))

#define LDSM_X4(r, addr) \
    asm volatile("ldmatrix.sync.aligned.m8n8.x4.shared.b16 {%0,%1,%2,%3}, [%4];" \
        : "=r"((r)[0]), "=r"((r)[1]), "=r"((r)[2]), "=r"((r)[3]) : "r"(addr))
#define LDSM_X4_T(r, addr) \
    asm volatile("ldmatrix.sync.aligned.m8n8.x4.trans.shared.b16 {%0,%1,%2,%3}, [%4];" \
        : "=r"((r)[0]), "=r"((r)[1]), "=r"((r)[2]), "=r"((r)[3]) : "r"(addr))

__device__ __forceinline__ unsigned smem_u32(const void* p) {
    return (unsigned)__cvta_generic_to_shared(p);
}
__device__ __forceinline__ unsigned pack_bf(__nv_bfloat16 lo, __nv_bfloat16 hi) {
    return ((unsigned)__bfloat16_as_ushort(hi) << 16) | __bfloat16_as_ushort(lo);
}

// ---------------------------------------------------------------------------
// splits (destinations bound in device code)
// DST 0: x -> fp16 single   DST 1: qkv_w -> fp16 single   DST 2: out_w -> bf16 hi/lo
// ---------------------------------------------------------------------------
template<int DST>
__global__ __launch_bounds__(256)
void split_kernel(const float4* __restrict__ src, int n4)
{
    int i = blockIdx.x * blockDim.x + threadIdx.x;
    if (i >= n4) return;
    float4 v = src[i];
    if (DST == 0 || DST == 1) {
        ushort4 h;
        h.x = __half_as_ushort(__float2half_rn(v.x));
        h.y = __half_as_ushort(__float2half_rn(v.y));
        h.z = __half_as_ushort(__float2half_rn(v.z));
        h.w = __half_as_ushort(__float2half_rn(v.w));
        if (DST == 0) ((ushort4*)g_xh)[i] = h;
        else          ((ushort4*)g_wqh)[i] = h;
    } else {
        ushort4 h, l;
#define SPLB(c, hc, lc) { \
        __nv_bfloat16 hb = __float2bfloat16_rn(v.c); \
        __nv_bfloat16 lb = __float2bfloat16_rn(v.c - __bfloat162float(hb)); \
        hc = __bfloat16_as_ushort(hb); lc = __bfloat16_as_ushort(lb); }
        SPLB(x, h.x, l.x) SPLB(y, h.y, l.y) SPLB(z, h.z, l.z) SPLB(w, h.w, l.w)
        ((ushort4*)g_woh)[i] = h; ((ushort4*)g_wol)[i] = l;
    }
}

// ---------------------------------------------------------------------------
// QKV GEMM (fp16 single-pass): CTA 128x256, 8 warps (2x4), warp tile 64x64.
// Per k16 step: 4 A-LDSM + 4 B-LDSM for 32 MMAs. smem 30KB static.
// ---------------------------------------------------------------------------
__global__ __launch_bounds__(256)
void gemm_qkv(const float* __restrict__ bias)
{
    __shared__ unsigned sA[128][20], sB[256][20];

    const int tid  = threadIdx.x;
    const int warp = tid >> 5;
    const int lane = tid & 31;
    const int g = lane >> 2;
    const int t = lane & 3;
    const int wm = (warp & 1) * 64;
    const int wn = (warp >> 1) * 64;
    const int m0 = blockIdx.y * 128;
    const int n0 = blockIdx.x * 256;

    const int lrow = tid >> 1;
    const int loff = (tid & 1) * 8;   // word offset within 16-word payload

    const __nv_bfloat16* Ap  = (const __nv_bfloat16*)g_xh  + (size_t)(m0 + lrow) * CC + loff * 2;
    const __nv_bfloat16* Bp0 = (const __nv_bfloat16*)g_wqh + (size_t)(n0 + lrow) * CC + loff * 2;
    const __nv_bfloat16* Bp1 = (const __nv_bfloat16*)g_wqh + (size_t)(n0 + 128 + lrow) * CC + loff * 2;

    const unsigned aOff = (unsigned)(wm + (lane & 15)) * 80u + (unsigned)(lane >> 4) * 16u;
    const unsigned bOff = (unsigned)(wn + (lane & 15)) * 80u + (unsigned)(lane >> 4) * 16u;
    const unsigned baseA = smem_u32(sA) + aOff;
    const unsigned baseB = smem_u32(sB) + bOff;

    float acc[4][8][4];
    #pragma unroll
    for (int i = 0; i < 4; ++i)
        #pragma unroll
        for (int j = 0; j < 8; ++j)
            #pragma unroll
            for (int e = 0; e < 4; ++e) acc[i][j][e] = 0.f;

    uint4 ra0, ra1, rb00, rb01, rb10, rb11;
#define LOAD_STAGE(kt) { \
        const int eo = (kt) * 32; \
        ra0  = *(const uint4*)(Ap  + eo); ra1  = *(const uint4*)(Ap  + eo + 8); \
        rb00 = *(const uint4*)(Bp0 + eo); rb01 = *(const uint4*)(Bp0 + eo + 8); \
        rb10 = *(const uint4*)(Bp1 + eo); rb11 = *(const uint4*)(Bp1 + eo + 8); }

    LOAD_STAGE(0);

    #pragma unroll 1
    for (int kt = 0; kt < 32; ++kt) {
        *(uint4*)&sA[lrow][loff]        = ra0;  *(uint4*)&sA[lrow][loff + 4]        = ra1;
        *(uint4*)&sB[lrow][loff]        = rb00; *(uint4*)&sB[lrow][loff + 4]        = rb01;
        *(uint4*)&sB[128 + lrow][loff]  = rb10; *(uint4*)&sB[128 + lrow][loff + 4]  = rb11;
        __syncthreads();

        if (kt + 1 < 32) LOAD_STAGE(kt + 1);

        #pragma unroll
        for (int ks = 0; ks < 2; ++ks) {
            const unsigned ko = (unsigned)ks * 32u;

            unsigned a4[4][4], b4[4][4];
            #pragma unroll
            for (int mt = 0; mt < 4; ++mt)
                LDSM_X4(a4[mt], baseA + (unsigned)mt * 1280u + ko);
            #pragma unroll
            for (int p = 0; p < 4; ++p)
                LDSM_X4(b4[p], baseB + (unsigned)p * 1280u + ko);

            #pragma unroll
            for (int mt = 0; mt < 4; ++mt)
                #pragma unroll
                for (int nt = 0; nt < 8; ++nt) {
                    const int p = nt >> 1, q = nt & 1;
                    unsigned bb[2] = { b4[p][q], b4[p][q + 2] };
                    MMA_F16(acc[mt][nt], a4[mt], bb);
                }
        }
        __syncthreads();
    }

    #pragma unroll
    for (int mt = 0; mt < 4; ++mt)
        #pragma unroll
        for (int nt = 0; nt < 8; ++nt)
            #pragma unroll
            for (int i = 0; i < 4; ++i) {
                const int m = m0 + wm + mt * 16 + g + (i >> 1) * 8;
                const int n = n0 + wn + nt * 8 + t * 2 + (i & 1);
                float v = acc[mt][nt][i] + bias[n];
                const int which = n >> 10;          // 0=q 1=k 2=v
                const int hc = n & 1023;
                const int h  = hc >> 6;
                const int d  = hc & 63;
                const int b  = m >> 11;
                const int tt = m & (TT - 1);
                __nv_bfloat16* dh = (which == 0) ? g_Qh : (which == 1) ? g_Kh : g_Vh;
                __nv_bfloat16* dl = (which == 0) ? g_Ql : (which == 1) ? g_Kl : g_Vl;
                if (which == 0) v *= 0.125f;        // 1/sqrt(64)
                __nv_bfloat16 hb = __float2bfloat16_rn(v);
                __nv_bfloat16 lb = __float2bfloat16_rn(v - __bfloat162float(hb));
                const size_t off = (size_t)((b*HH + h)*TT + tt) * HD + d;
                dh[off] = hb; dl[off] = lb;
            }
}

// ---------------------------------------------------------------------------
// Out-projection GEMM (bf16x3, mma.sync) — unchanged from R14 (passing).
// ---------------------------------------------------------------------------
__global__ __launch_bounds__(256)
void gemm_out(const float* __restrict__ bias, float* __restrict__ out)
{
    __shared__ unsigned sAh[128][20], sAl[128][20], sBh[128][20], sBl[128][20];

    const int tid  = threadIdx.x;
    const int warp = tid >> 5;
    const int lane = tid & 31;
    const int g = lane >> 2;
    const int t = lane & 3;
    const int wm = (warp & 1) * 64;
    const int wn = (warp >> 1) * 32;
    const int m0 = blockIdx.y * 128;
    const int n0 = blockIdx.x * 128;

    const int lrow = tid >> 1;
    const int loff = (tid & 1) * 8;

    const __nv_bfloat16* Ap  = g_ah  + (size_t)(m0 + lrow) * CC + loff * 2;
    const __nv_bfloat16* Alp = g_al  + (size_t)(m0 + lrow) * CC + loff * 2;
    const __nv_bfloat16* Bp  = g_woh + (size_t)(n0 + lrow) * CC + loff * 2;
    const __nv_bfloat16* Blp = g_wol + (size_t)(n0 + lrow) * CC + loff * 2;

    const unsigned aOff = (unsigned)(wm + (lane & 15)) * 80u + (unsigned)(lane >> 4) * 16u;
    const unsigned bOff = (unsigned)(wn + (lane & 15)) * 80u + (unsigned)(lane >> 4) * 16u;
    const unsigned baseAh = smem_u32(sAh) + aOff;
    const unsigned baseAl = smem_u32(sAl) + aOff;
    const unsigned baseBh = smem_u32(sBh) + bOff;
    const unsigned baseBl = smem_u32(sBl) + bOff;

    float acc[4][4][4];
    #pragma unroll
    for (int i = 0; i < 4; ++i)
        #pragma unroll
        for (int j = 0; j < 4; ++j)
            #pragma unroll
            for (int e = 0; e < 4; ++e) acc[i][j][e] = 0.f;

    uint4 rah0, rah1, ral0, ral1, rbh0, rbh1, rbl0, rbl1;
#define LOAD_STAGE_O(kt) { \
        const int eo = (kt) * 32; \
        rah0 = *(const uint4*)(Ap  + eo); rah1 = *(const uint4*)(Ap  + eo + 8); \
        ral0 = *(const uint4*)(Alp + eo); ral1 = *(const uint4*)(Alp + eo + 8); \
        rbh0 = *(const uint4*)(Bp  + eo); rbh1 = *(const uint4*)(Bp  + eo + 8); \
        rbl0 = *(const uint4*)(Blp + eo); rbl1 = *(const uint4*)(Blp + eo + 8); }

    LOAD_STAGE_O(0);

    #pragma unroll 1
    for (int kt = 0; kt < 32; ++kt) {
        *(uint4*)&sAh[lrow][loff]     = rah0; *(uint4*)&sAh[lrow][loff + 4] = rah1;
        *(uint4*)&sAl[lrow][loff]     = ral0; *(uint4*)&sAl[lrow][loff + 4] = ral1;
        *(uint4*)&sBh[lrow][loff]     = rbh0; *(uint4*)&sBh[lrow][loff + 4] = rbh1;
        *(uint4*)&sBl[lrow][loff]     = rbl0; *(uint4*)&sBl[lrow][loff + 4] = rbl1;
        __syncthreads();

        if (kt + 1 < 32) LOAD_STAGE_O(kt + 1);

        #pragma unroll
        for (int ks = 0; ks < 2; ++ks) {
            const unsigned ko = (unsigned)ks * 32u;

            unsigned ah[4][4], al[4][4], bh4[2][4], bl4[2][4];
            #pragma unroll
            for (int mt = 0; mt < 4; ++mt) {
                LDSM_X4(ah[mt], baseAh + (unsigned)mt * 1280u + ko);
                LDSM_X4(al[mt], baseAl + (unsigned)mt * 1280u + ko);
            }
            #pragma unroll
            for (int p = 0; p < 2; ++p) {
                LDSM_X4(bh4[p], baseBh + (unsigned)p * 1280u + ko);
                LDSM_X4(bl4[p], baseBl + (unsigned)p * 1280u + ko);
            }
            #pragma unroll
            for (int mt = 0; mt < 4; ++mt)
                #pragma unroll
                for (int nt = 0; nt < 4; ++nt) {
                    const int p = nt >> 1, q = nt & 1;
                    unsigned bh[2] = { bh4[p][q], bh4[p][q + 2] };
                    unsigned bl[2] = { bl4[p][q], bl4[p][q + 2] };
                    MMA_BF16(acc[mt][nt], ah[mt], bh);
                    MMA_BF16(acc[mt][nt], ah[mt], bl);
                    MMA_BF16(acc[mt][nt], al[mt], bh);
                }
        }
        __syncthreads();
    }

    #pragma unroll
    for (int mt = 0; mt < 4; ++mt)
        #pragma unroll
        for (int nt = 0; nt < 4; ++nt)
            #pragma unroll
            for (int i = 0; i < 4; ++i) {
                const int m = m0 + wm + mt * 16 + g + (i >> 1) * 8;
                const int n = n0 + wn + nt * 8 + t * 2 + (i & 1);
                out[(size_t)m * CC + n] = acc[mt][nt][i] + bias[n];
            }
}

// ---------------------------------------------------------------------------
// Tensor-core causal flash attention (bf16x3) — unchanged from R14 (passing).
// ---------------------------------------------------------------------------
__global__ __launch_bounds__(128)
void attn_mma()
{
    __shared__ __align__(16) __nv_bfloat16 sQh[64*QS], sQl[64*QS];
    __shared__ __align__(16) __nv_bfloat16 sKVh[64*QS], sKVl[64*QS];

    const int tid  = threadIdx.x;
    const int warp = tid >> 5;
    const int lane = tid & 31;
    const int g = lane >> 2;
    const int t = lane & 3;
    const int q0 = blockIdx.x * 64;
    const int bh = blockIdx.y;
    const size_t gbase = (size_t)bh * TT * HD;

    #pragma unroll
    for (int idx = tid; idx < 512; idx += 128) {
        const int r = idx >> 3, c = idx & 7;
        const size_t go = gbase + (size_t)(q0 + r) * HD + c * 8;
        *(uint4*)&sQh[r*QS + c*8] = *(const uint4*)&g_Qh[go];
        *(uint4*)&sQl[r*QS + c*8] = *(const uint4*)&g_Ql[go];
    }

    const unsigned qOff = (unsigned)(warp*16 + (lane & 15)) * 144u + (unsigned)(lane >> 4) * 16u;
    const unsigned kOff = (unsigned)(((lane >> 4) & 1) * 8 + (lane & 7)) * 144u
                        + (unsigned)((lane >> 3) & 1) * 16u;
    const unsigned vOff = (unsigned)(((lane >> 3) & 1) * 8 + (lane & 7)) * 144u
                        + (unsigned)((lane >> 4) & 1) * 16u;
    const unsigned qbh = smem_u32(sQh)  + qOff, qbl = smem_u32(sQl)  + qOff;
    const unsigned kbh = smem_u32(sKVh) + kOff, kbl = smem_u32(sKVl) + kOff;
    const unsigned vbh = smem_u32(sKVh) + vOff, vbl = smem_u32(sKVl) + vOff;

    float m_i[2] = {-1e30f, -1e30f}, l_i[2] = {0.f, 0.f};
    float oacc[8][4];
    #pragma unroll
    for (int i = 0; i < 8; ++i)
        #pragma unroll
        for (int e = 0; e < 4; ++e) oacc[i][e] = 0.f;

    #pragma unroll 1
    for (int j0 = 0; j0 <= q0; j0 += 64) {
        __syncthreads();
        #pragma unroll
        for (int idx = tid; idx < 512; idx += 128) {
            const int r = idx >> 3, c = idx & 7;
            const size_t go = gbase + (size_t)(j0 + r) * HD + c * 8;
            *(uint4*)&sKVh[r*QS + c*8] = *(const uint4*)&g_Kh[go];
            *(uint4*)&sKVl[r*QS + c*8] = *(const uint4*)&g_Kl[go];
        }
        __syncthreads();

        float sacc[8][4];
        #pragma unroll
        for (int i = 0; i < 8; ++i)
            #pragma unroll
            for (int e = 0; e < 4; ++e) sacc[i][e] = 0.f;

        #pragma unroll
        for (int kc = 0; kc < 4; ++kc) {
            unsigned qh[4], ql[4];
            LDSM_X4(qh, qbh + kc*32u);
            LDSM_X4(ql, qbl + kc*32u);
            #pragma unroll
            for (int ntp = 0; ntp < 4; ++ntp) {
                unsigned kh[4], kl[4];
                LDSM_X4(kh, kbh + (unsigned)ntp*2304u + kc*32u);
                LDSM_X4(kl, kbl + (unsigned)ntp*2304u + kc*32u);
                MMA_BF16(sacc[2*ntp],   qh, kh);
                MMA_BF16(sacc[2*ntp],   qh, kl);
                MMA_BF16(sacc[2*ntp],   ql, kh);
                MMA_BF16(sacc[2*ntp+1], qh, kh + 2);
                MMA_BF16(sacc[2*ntp+1], qh, kl + 2);
                MMA_BF16(sacc[2*ntp+1], ql, kh + 2);
            }
        }

        if (j0 == q0) {
            const int rbase = q0 + warp*16;
            #pragma unroll
            for (int nt = 0; nt < 8; ++nt)
                #pragma unroll
                for (int e = 0; e < 4; ++e) {
                    const int col = j0 + nt*8 + t*2 + (e & 1);
                    const int row = rbase + g + (e >> 1)*8;
                    if (col > row) sacc[nt][e] = -1e30f;
                }
        }

        #pragma unroll
        for (int h2 = 0; h2 < 2; ++h2) {
            float mloc = -1e30f;
            #pragma unroll
            for (int nt = 0; nt < 8; ++nt)
                mloc = fmaxf(mloc, fmaxf(sacc[nt][2*h2], sacc[nt][2*h2+1]));
            mloc = fmaxf(mloc, __shfl_xor_sync(0xffffffffu, mloc, 1));
            mloc = fmaxf(mloc, __shfl_xor_sync(0xffffffffu, mloc, 2));
            const float mnew = fmaxf(m_i[h2], mloc);
            const float corr = __expf(m_i[h2] - mnew);
            float sum = 0.f;
            #pragma unroll
            for (int nt = 0; nt < 8; ++nt) {
                const float p0 = __expf(sacc[nt][2*h2]   - mnew);
                const float p1 = __expf(sacc[nt][2*h2+1] - mnew);
                sacc[nt][2*h2] = p0; sacc[nt][2*h2+1] = p1;
                sum += p0 + p1;
            }
            sum += __shfl_xor_sync(0xffffffffu, sum, 1);
            sum += __shfl_xor_sync(0xffffffffu, sum, 2);
            l_i[h2] = l_i[h2] * corr + sum;
            m_i[h2] = mnew;
            #pragma unroll
            for (int dt = 0; dt < 8; ++dt) {
                oacc[dt][2*h2] *= corr; oacc[dt][2*h2+1] *= corr;
            }
        }

        __syncthreads();
        #pragma unroll
        for (int idx = tid; idx < 512; idx += 128) {
            const int r = idx >> 3, c = idx & 7;
            const size_t go = gbase + (size_t)(j0 + r) * HD + c * 8;
            *(uint4*)&sKVh[r*QS + c*8] = *(const uint4*)&g_Vh[go];
            *(uint4*)&sKVl[r*QS + c*8] = *(const uint4*)&g_Vl[go];
        }
        __syncthreads();

        #pragma unroll
        for (int kc = 0; kc < 4; ++kc) {
            unsigned ph[4], pl[4];
            #pragma unroll
            for (int u = 0; u < 4; ++u) {
                const int nt = 2*kc + (u >> 1);
                const float a0 = sacc[nt][(u & 1)*2], a1 = sacc[nt][(u & 1)*2 + 1];
                const __nv_bfloat16 h0 = __float2bfloat16_rn(a0);
                const __nv_bfloat16 h1 = __float2bfloat16_rn(a1);
                ph[u] = pack_bf(h0, h1);
                pl[u] = pack_bf(__float2bfloat16_rn(a0 - __bfloat162float(h0)),
                                __float2bfloat16_rn(a1 - __bfloat162float(h1)));
            }
            #pragma unroll
            for (int dtp = 0; dtp < 4; ++dtp) {
                unsigned vh[4], vl[4];
                LDSM_X4_T(vh, vbh + (unsigned)kc*2304u + dtp*32u);
                LDSM_X4_T(vl, vbl + (unsigned)kc*2304u + dtp*32u);
                MMA_BF16(oacc[2*dtp],   ph, vh);
                MMA_BF16(oacc[2*dtp],   ph, vl);
                MMA_BF16(oacc[2*dtp],   pl, vh);
                MMA_BF16(oacc[2*dtp+1], ph, vh + 2);
                MMA_BF16(oacc[2*dtp+1], ph, vl + 2);
                MMA_BF16(oacc[2*dtp+1], pl, vh + 2);
            }
        }
    }

    const int b  = bh >> 4;
    const int hh = bh & 15;
    #pragma unroll
    for (int h2 = 0; h2 < 2; ++h2) {
        const float inv = 1.f / l_i[h2];
        const int r = q0 + warp*16 + g + h2*8;
        const size_t rowoff = (size_t)(b*TT + r) * CC + hh*HD;
        #pragma unroll
        for (int dt = 0; dt < 8; ++dt) {
            const float o0 = oacc[dt][2*h2] * inv;
            const float o1 = oacc[dt][2*h2+1] * inv;
            const __nv_bfloat16 h0 = __float2bfloat16_rn(o0);
            const __nv_bfloat16 h1 = __float2bfloat16_rn(o1);
            const unsigned wh = pack_bf(h0, h1);
            const unsigned wl = pack_bf(__float2bfloat16_rn(o0 - __bfloat162float(h0)),
                                        __float2bfloat16_rn(o1 - __bfloat162float(h1)));
            *(unsigned*)&g_ah[rowoff + dt*8 + t*2] = wh;
            *(unsigned*)&g_al[rowoff + dt*8 + t*2] = wl;
        }
    }
}

// ---------------------------------------------------------------------------
extern "C" void kernel_launch(void* const* d_in, const int* in_sizes, int n_in,
                              void* d_out, int out_size)
{
    const float* x     = (const float*)d_in[0];
    const float* qkv_b = (const float*)d_in[2];
    const float* out_b = (const float*)d_in[4];
    float* y = (float*)d_out;

    {
        int n4 = MM*CC/4;
        split_kernel<0><<<(n4+255)/256, 256>>>((const float4*)x, n4);
    }
    {
        int n4 = 3*CC*CC/4;
        split_kernel<1><<<(n4+255)/256, 256>>>((const float4*)d_in[1], n4);
    }
    {
        int n4 = CC*CC/4;
        split_kernel<2><<<(n4+255)/256, 256>>>((const float4*)d_in[3], n4);
    }

    // 1) QKV projection (fp16 single-pass) -> Q/K/V bf16 hi/lo
    gemm_qkv<<<dim3(3*CC/256, MM/128), 256>>>(qkv_b);
    // 2) causal attention (bf16x3) -> g_ah/g_al
    attn_mma<<<dim3(TT/64, BB*HH), 128>>>();
    // 3) output projection (bf16x3)
    gemm_out<<<dim3(CC/128, MM/128), 256>>>(out_b, y);
}